// round 2
// baseline (speedup 1.0000x reference)
#include <cuda_runtime.h>
#include <cuda_bf16.h>

#define NN 40000
#define EE 1280000
#define FF 64
#define HH 128
#define RR 20
#define CC 32
#define GG 256

// Scratch (static device globals; no allocation at runtime)
__device__ float g_sums[(size_t)NN * RR * HH];   // reused: layer1 uses first NN*RR*FF
__device__ float g_cnt[NN * RR];
__device__ float g_inv[NN * RR];
__device__ float g_h1[(size_t)NN * HH];
__device__ float g_h2[(size_t)NN * HH];
__device__ float g_pool[GG * HH];
__device__ float g_pcnt[GG];

__global__ void count_kernel(const int* __restrict__ ei,
                             const int* __restrict__ et) {
    int e = blockIdx.x * blockDim.x + threadIdx.x;
    if (e >= EE) return;
    int dst = ei[EE + e];
    int r = et[e];
    atomicAdd(&g_cnt[dst * RR + r], 1.0f);
}

__global__ void inv_kernel() {
    int i = blockIdx.x * blockDim.x + threadIdx.x;
    if (i < NN * RR) g_inv[i] = 1.0f / fmaxf(g_cnt[i], 1.0f);
}

template <int FIN>
__global__ void scatter_kernel(const float* __restrict__ x,
                               const int* __restrict__ ei,
                               const int* __restrict__ et) {
    constexpr int CPE = FIN / 4;
    long long tid = (long long)blockIdx.x * blockDim.x + threadIdx.x;
    if (tid >= (long long)EE * CPE) return;
    int e = (int)(tid / CPE);
    int c = (int)(tid % CPE);
    int src = ei[e];
    int dst = ei[EE + e];
    int r = et[e];
    float4 v = reinterpret_cast<const float4*>(x + (size_t)src * FIN)[c];
    float* p = &g_sums[(size_t)(dst * RR + r) * FIN + c * 4];
    atomicAdd(p + 0, v.x);
    atomicAdd(p + 1, v.y);
    atomicAdd(p + 2, v.z);
    atomicAdd(p + 3, v.w);
}

// out[N,H] = relu( Ahat[N, R*FIN] @ W[R*FIN, H] + xin @ root + bias )
// Ahat[n, r*FIN+f] = g_sums[n, r, f] * g_inv[n, r]
template <int FIN>
__global__ __launch_bounds__(256) void gemm_kernel(
    const float* __restrict__ xin,   // [NN, FIN]
    const float* __restrict__ W,     // [RR*FIN, HH]
    const float* __restrict__ root,  // [FIN, HH]
    const float* __restrict__ bias,  // [HH]
    float* __restrict__ out)         // [NN, HH]
{
    constexpr int BM = 64, BN = 128, BK = 16;
    constexpr int K1 = RR * FIN;
    constexpr int SHIFT = (FIN == 64) ? 6 : 7;

    __shared__ float As[BK][BM];
    __shared__ float Bs[BK][BN];

    const int t = threadIdx.x;
    const int n0 = blockIdx.x * BM;
    const int aRow = t >> 2;         // 0..63
    const int aK = (t & 3) * 4;      // 0,4,8,12
    const int bRow = t >> 5;         // 0..7
    const int bCol = (t & 31) * 4;   // 0..124
    const int ty = t >> 4;           // 0..15
    const int tx = t & 15;           // 0..15

    float acc[4][8];
#pragma unroll
    for (int i = 0; i < 4; i++)
#pragma unroll
        for (int j = 0; j < 8; j++) acc[i][j] = 0.f;

    // Phase 1: relation-aggregate part (scaled by inv count; BK tile never
    // straddles a relation boundary since FIN % BK == 0)
    for (int k0 = 0; k0 < K1; k0 += BK) {
        float scale = g_inv[(size_t)(n0 + aRow) * RR + (k0 >> SHIFT)];
        float4 a = *reinterpret_cast<const float4*>(
            &g_sums[(size_t)(n0 + aRow) * K1 + k0 + aK]);
        As[aK + 0][aRow] = a.x * scale;
        As[aK + 1][aRow] = a.y * scale;
        As[aK + 2][aRow] = a.z * scale;
        As[aK + 3][aRow] = a.w * scale;
        float4 w0 = *reinterpret_cast<const float4*>(&W[(size_t)(k0 + bRow) * BN + bCol]);
        float4 w1 = *reinterpret_cast<const float4*>(&W[(size_t)(k0 + bRow + 8) * BN + bCol]);
        *reinterpret_cast<float4*>(&Bs[bRow][bCol]) = w0;
        *reinterpret_cast<float4*>(&Bs[bRow + 8][bCol]) = w1;
        __syncthreads();
#pragma unroll
        for (int kk = 0; kk < BK; kk++) {
            float4 av = *reinterpret_cast<float4*>(&As[kk][ty * 4]);
            float4 bv0 = *reinterpret_cast<float4*>(&Bs[kk][tx * 8]);
            float4 bv1 = *reinterpret_cast<float4*>(&Bs[kk][tx * 8 + 4]);
            float a4[4] = {av.x, av.y, av.z, av.w};
            float b8[8] = {bv0.x, bv0.y, bv0.z, bv0.w, bv1.x, bv1.y, bv1.z, bv1.w};
#pragma unroll
            for (int i = 0; i < 4; i++)
#pragma unroll
                for (int j = 0; j < 8; j++) acc[i][j] += a4[i] * b8[j];
        }
        __syncthreads();
    }

    // Phase 2: root (self-loop) part
    for (int k0 = 0; k0 < FIN; k0 += BK) {
        float4 a = *reinterpret_cast<const float4*>(
            &xin[(size_t)(n0 + aRow) * FIN + k0 + aK]);
        As[aK + 0][aRow] = a.x;
        As[aK + 1][aRow] = a.y;
        As[aK + 2][aRow] = a.z;
        As[aK + 3][aRow] = a.w;
        float4 w0 = *reinterpret_cast<const float4*>(&root[(size_t)(k0 + bRow) * BN + bCol]);
        float4 w1 = *reinterpret_cast<const float4*>(&root[(size_t)(k0 + bRow + 8) * BN + bCol]);
        *reinterpret_cast<float4*>(&Bs[bRow][bCol]) = w0;
        *reinterpret_cast<float4*>(&Bs[bRow + 8][bCol]) = w1;
        __syncthreads();
#pragma unroll
        for (int kk = 0; kk < BK; kk++) {
            float4 av = *reinterpret_cast<float4*>(&As[kk][ty * 4]);
            float4 bv0 = *reinterpret_cast<float4*>(&Bs[kk][tx * 8]);
            float4 bv1 = *reinterpret_cast<float4*>(&Bs[kk][tx * 8 + 4]);
            float a4[4] = {av.x, av.y, av.z, av.w};
            float b8[8] = {bv0.x, bv0.y, bv0.z, bv0.w, bv1.x, bv1.y, bv1.z, bv1.w};
#pragma unroll
            for (int i = 0; i < 4; i++)
#pragma unroll
                for (int j = 0; j < 8; j++) acc[i][j] += a4[i] * b8[j];
        }
        __syncthreads();
    }

#pragma unroll
    for (int i = 0; i < 4; i++) {
        int m = n0 + ty * 4 + i;
#pragma unroll
        for (int j = 0; j < 8; j++) {
            int h = tx * 8 + j;
            float v = acc[i][j] + bias[h];
            v = fmaxf(v, 0.f);
            out[(size_t)m * HH + h] = v;
        }
    }
}

__global__ void pcnt_kernel(const int* __restrict__ batch) {
    int n = blockIdx.x * blockDim.x + threadIdx.x;
    if (n < NN) atomicAdd(&g_pcnt[batch[n]], 1.0f);
}

__global__ void pool_kernel(const int* __restrict__ batch) {
    int tid = blockIdx.x * blockDim.x + threadIdx.x;
    if (tid >= NN * (HH / 4)) return;
    int n = tid / (HH / 4);
    int c = tid % (HH / 4);
    int g = batch[n];
    float4 v = reinterpret_cast<const float4*>(g_h2)[tid];
    float* p = &g_pool[g * HH + c * 4];
    atomicAdd(p + 0, v.x);
    atomicAdd(p + 1, v.y);
    atomicAdd(p + 2, v.z);
    atomicAdd(p + 3, v.w);
}

__global__ void final_kernel(const float* __restrict__ fc_w,
                             const float* __restrict__ fc_b,
                             float* __restrict__ out) {
    int g = blockIdx.x;
    int c = threadIdx.x;
    float inv = 1.0f / fmaxf(g_pcnt[g], 1.0f);
    float acc = 0.f;
#pragma unroll 8
    for (int h = 0; h < HH; h++) acc += g_pool[g * HH + h] * fc_w[h * CC + c];
    out[g * CC + c] = acc * inv + fc_b[c];
}

extern "C" void kernel_launch(void* const* d_in, const int* in_sizes, int n_in,
                              void* d_out, int out_size) {
    const float* x     = (const float*)d_in[0];
    const int* ei      = (const int*)d_in[1];   // int32: JAX x64 disabled canonicalizes int64->int32
    const int* et      = (const int*)d_in[2];
    const int* bat     = (const int*)d_in[3];
    const float* W1    = (const float*)d_in[4];
    const float* root1 = (const float*)d_in[5];
    const float* b1    = (const float*)d_in[6];
    const float* W2    = (const float*)d_in[7];
    const float* root2 = (const float*)d_in[8];
    const float* b2    = (const float*)d_in[9];
    const float* fcw   = (const float*)d_in[10];
    const float* fcb   = (const float*)d_in[11];
    float* out         = (float*)d_out;

    void *p_sums, *p_cnt, *p_pool, *p_pcnt, *p_h1, *p_h2;
    cudaGetSymbolAddress(&p_sums, g_sums);
    cudaGetSymbolAddress(&p_cnt, g_cnt);
    cudaGetSymbolAddress(&p_pool, g_pool);
    cudaGetSymbolAddress(&p_pcnt, g_pcnt);
    cudaGetSymbolAddress(&p_h1, g_h1);
    cudaGetSymbolAddress(&p_h2, g_h2);
    float* h1 = (float*)p_h1;
    float* h2 = (float*)p_h2;

    // Edge counts per (dst, relation) — shared by both layers
    cudaMemsetAsync(p_cnt, 0, sizeof(float) * NN * RR, 0);
    count_kernel<<<(EE + 255) / 256, 256>>>(ei, et);
    inv_kernel<<<(NN * RR + 255) / 256, 256>>>();

    // Layer 1
    cudaMemsetAsync(p_sums, 0, sizeof(float) * (size_t)NN * RR * FF, 0);
    scatter_kernel<FF><<<(EE * (FF / 4) + 255) / 256, 256>>>(x, ei, et);
    gemm_kernel<FF><<<NN / 64, 256>>>(x, W1, root1, b1, h1);

    // Layer 2
    cudaMemsetAsync(p_sums, 0, sizeof(float) * (size_t)NN * RR * HH, 0);
    scatter_kernel<HH><<<(EE * (HH / 4) + 255) / 256, 256>>>(h1, ei, et);
    gemm_kernel<HH><<<NN / 64, 256>>>(h1, W2, root2, b2, h2);

    // Global mean pool + FC
    cudaMemsetAsync(p_pool, 0, sizeof(float) * GG * HH, 0);
    cudaMemsetAsync(p_pcnt, 0, sizeof(float) * GG, 0);
    pcnt_kernel<<<(NN + 255) / 256, 256>>>(bat);
    pool_kernel<<<(NN * (HH / 4) + 255) / 256, 256>>>(bat);
    final_kernel<<<GG, CC>>>(fcw, fcb, out);
}

// round 3
// speedup vs baseline: 1.4118x; 1.4118x over previous
#include <cuda_runtime.h>
#include <cuda_bf16.h>

#define NN 40000
#define EE 1280000
#define FF 64
#define HH 128
#define RR 20
#define CC 32
#define GG 256

// Scratch (static device globals; no allocation at runtime)
__device__ float g_sums[(size_t)NN * RR * HH];   // reused: layer1 uses first NN*RR*FF
__device__ float g_cnt[NN * RR];
__device__ float g_inv[NN * RR];
__device__ float g_h1[(size_t)NN * HH];
__device__ float g_h2[(size_t)NN * HH];
__device__ float g_pool[GG * HH];
__device__ float g_pcnt[GG];

__global__ void count_kernel(const int* __restrict__ ei,
                             const int* __restrict__ et) {
    int e = blockIdx.x * blockDim.x + threadIdx.x;
    if (e >= EE) return;
    int dst = ei[EE + e];
    int r = et[e];
    atomicAdd(&g_cnt[dst * RR + r], 1.0f);
}

__global__ void inv_kernel() {
    int i = blockIdx.x * blockDim.x + threadIdx.x;
    if (i < NN * RR) g_inv[i] = 1.0f / fmaxf(g_cnt[i], 1.0f);
}

__device__ __forceinline__ void red_add_v4(float* p, float4 v) {
    asm volatile("red.global.add.v4.f32 [%0], {%1, %2, %3, %4};"
                 :: "l"(p), "f"(v.x), "f"(v.y), "f"(v.z), "f"(v.w)
                 : "memory");
}

template <int FIN>
__global__ void scatter_kernel(const float* __restrict__ x,
                               const int* __restrict__ ei,
                               const int* __restrict__ et) {
    constexpr int CPE = FIN / 4;
    long long tid = (long long)blockIdx.x * blockDim.x + threadIdx.x;
    if (tid >= (long long)EE * CPE) return;
    int e = (int)(tid / CPE);
    int c = (int)(tid % CPE);
    int src = ei[e];
    int dst = ei[EE + e];
    int r = et[e];
    float4 v = reinterpret_cast<const float4*>(x + (size_t)src * FIN)[c];
    float* p = &g_sums[(size_t)(dst * RR + r) * FIN + c * 4];
    red_add_v4(p, v);
}

// out[N,H] = relu( Ahat[N, R*FIN] @ W[R*FIN, H] + xin @ root + bias )
// Ahat[n, r*FIN+f] = g_sums[n, r, f] * g_inv[n, r]
// One virtual K of length R*FIN + FIN: first part from g_sums*inv vs W,
// tail from xin vs root.
template <int FIN>
__global__ __launch_bounds__(256, 2) void gemm_kernel(
    const float* __restrict__ xin,   // [NN, FIN]
    const float* __restrict__ W,     // [RR*FIN, HH]
    const float* __restrict__ root,  // [FIN, HH]
    const float* __restrict__ bias,  // [HH]
    float* __restrict__ out)         // [NN, HH]
{
    constexpr int BM = 128, BN = 128, BK = 8;
    constexpr int K1 = RR * FIN;
    constexpr int KT = K1 + FIN;
    constexpr int NTILES = KT / BK;
    constexpr int SHIFT = (FIN == 64) ? 6 : 7;

    __shared__ float As[BK][BM + 4];
    __shared__ float Bs[BK][BN];

    const int t = threadIdx.x;
    const int m0 = blockIdx.x * BM;
    const int aRow = t >> 1;          // 0..127
    const int aK = (t & 1) * 4;       // 0 or 4
    const int bRow = t >> 5;          // 0..7
    const int bCol = (t & 31) * 4;    // 0..124
    const int tx = t & 15;
    const int ty = t >> 4;

    int rowL = m0 + aRow;
    if (rowL >= NN) rowL = NN - 1;    // clamp loads; stores guarded

    float acc[8][8];
#pragma unroll
    for (int i = 0; i < 8; i++)
#pragma unroll
        for (int j = 0; j < 8; j++) acc[i][j] = 0.f;

    float4 aReg, bReg;

    // ---- load tile 0 ----
    {
        float scale = g_inv[(size_t)rowL * RR + 0];
        float4 a = *reinterpret_cast<const float4*>(&g_sums[(size_t)rowL * K1 + aK]);
        aReg = make_float4(a.x * scale, a.y * scale, a.z * scale, a.w * scale);
        bReg = *reinterpret_cast<const float4*>(&W[(size_t)bRow * BN + bCol]);
    }
    As[aK + 0][aRow] = aReg.x;
    As[aK + 1][aRow] = aReg.y;
    As[aK + 2][aRow] = aReg.z;
    As[aK + 3][aRow] = aReg.w;
    *reinterpret_cast<float4*>(&Bs[bRow][bCol]) = bReg;
    __syncthreads();

    for (int tile = 1; tile <= NTILES; tile++) {
        const bool more = (tile < NTILES);
        if (more) {
            int k0 = tile * BK;
            if (k0 < K1) {
                float scale = g_inv[(size_t)rowL * RR + (k0 >> SHIFT)];
                float4 a = *reinterpret_cast<const float4*>(
                    &g_sums[(size_t)rowL * K1 + k0 + aK]);
                aReg = make_float4(a.x * scale, a.y * scale, a.z * scale, a.w * scale);
                bReg = *reinterpret_cast<const float4*>(
                    &W[(size_t)(k0 + bRow) * BN + bCol]);
            } else {
                int kk = k0 - K1;
                aReg = *reinterpret_cast<const float4*>(
                    &xin[(size_t)rowL * FIN + kk + aK]);
                bReg = *reinterpret_cast<const float4*>(
                    &root[(size_t)(kk + bRow) * BN + bCol]);
            }
        }

        // ---- compute current tile ----
#pragma unroll
        for (int kk = 0; kk < BK; kk++) {
            float a[8], b[8];
            *reinterpret_cast<float4*>(&a[0]) =
                *reinterpret_cast<const float4*>(&As[kk][ty * 4]);
            *reinterpret_cast<float4*>(&a[4]) =
                *reinterpret_cast<const float4*>(&As[kk][64 + ty * 4]);
            *reinterpret_cast<float4*>(&b[0]) =
                *reinterpret_cast<const float4*>(&Bs[kk][tx * 4]);
            *reinterpret_cast<float4*>(&b[4]) =
                *reinterpret_cast<const float4*>(&Bs[kk][64 + tx * 4]);
#pragma unroll
            for (int i = 0; i < 8; i++)
#pragma unroll
                for (int j = 0; j < 8; j++)
                    acc[i][j] = fmaf(a[i], b[j], acc[i][j]);
        }
        __syncthreads();

        if (more) {
            As[aK + 0][aRow] = aReg.x;
            As[aK + 1][aRow] = aReg.y;
            As[aK + 2][aRow] = aReg.z;
            As[aK + 3][aRow] = aReg.w;
            *reinterpret_cast<float4*>(&Bs[bRow][bCol]) = bReg;
            __syncthreads();
        }
    }

    // ---- epilogue: bias + relu ----
    float bv[8];
#pragma unroll
    for (int j = 0; j < 4; j++) {
        bv[j] = bias[tx * 4 + j];
        bv[4 + j] = bias[64 + tx * 4 + j];
    }
#pragma unroll
    for (int ih = 0; ih < 2; ih++) {
#pragma unroll
        for (int i = 0; i < 4; i++) {
            int m = m0 + ih * 64 + ty * 4 + i;
            if (m < NN) {
#pragma unroll
                for (int jh = 0; jh < 2; jh++) {
                    float4 v;
                    v.x = fmaxf(acc[ih * 4 + i][jh * 4 + 0] + bv[jh * 4 + 0], 0.f);
                    v.y = fmaxf(acc[ih * 4 + i][jh * 4 + 1] + bv[jh * 4 + 1], 0.f);
                    v.z = fmaxf(acc[ih * 4 + i][jh * 4 + 2] + bv[jh * 4 + 2], 0.f);
                    v.w = fmaxf(acc[ih * 4 + i][jh * 4 + 3] + bv[jh * 4 + 3], 0.f);
                    *reinterpret_cast<float4*>(
                        &out[(size_t)m * HH + jh * 64 + tx * 4]) = v;
                }
            }
        }
    }
}

__global__ void pcnt_kernel(const int* __restrict__ batch) {
    int n = blockIdx.x * blockDim.x + threadIdx.x;
    if (n < NN) atomicAdd(&g_pcnt[batch[n]], 1.0f);
}

__global__ void pool_kernel(const int* __restrict__ batch) {
    int tid = blockIdx.x * blockDim.x + threadIdx.x;
    if (tid >= NN * (HH / 4)) return;
    int n = tid / (HH / 4);
    int c = tid % (HH / 4);
    int g = batch[n];
    float4 v = reinterpret_cast<const float4*>(g_h2)[tid];
    red_add_v4(&g_pool[g * HH + c * 4], v);
}

__global__ void final_kernel(const float* __restrict__ fc_w,
                             const float* __restrict__ fc_b,
                             float* __restrict__ out) {
    int g = blockIdx.x;
    int c = threadIdx.x;
    float inv = 1.0f / fmaxf(g_pcnt[g], 1.0f);
    float acc = 0.f;
#pragma unroll 8
    for (int h = 0; h < HH; h++) acc += g_pool[g * HH + h] * fc_w[h * CC + c];
    out[g * CC + c] = acc * inv + fc_b[c];
}

extern "C" void kernel_launch(void* const* d_in, const int* in_sizes, int n_in,
                              void* d_out, int out_size) {
    const float* x     = (const float*)d_in[0];
    const int* ei      = (const int*)d_in[1];   // int32 (JAX canonicalizes int64->int32)
    const int* et      = (const int*)d_in[2];
    const int* bat     = (const int*)d_in[3];
    const float* W1    = (const float*)d_in[4];
    const float* root1 = (const float*)d_in[5];
    const float* b1    = (const float*)d_in[6];
    const float* W2    = (const float*)d_in[7];
    const float* root2 = (const float*)d_in[8];
    const float* b2    = (const float*)d_in[9];
    const float* fcw   = (const float*)d_in[10];
    const float* fcb   = (const float*)d_in[11];
    float* out         = (float*)d_out;

    void *p_sums, *p_cnt, *p_pool, *p_pcnt, *p_h1, *p_h2;
    cudaGetSymbolAddress(&p_sums, g_sums);
    cudaGetSymbolAddress(&p_cnt, g_cnt);
    cudaGetSymbolAddress(&p_pool, g_pool);
    cudaGetSymbolAddress(&p_pcnt, g_pcnt);
    cudaGetSymbolAddress(&p_h1, g_h1);
    cudaGetSymbolAddress(&p_h2, g_h2);
    float* h1 = (float*)p_h1;
    float* h2 = (float*)p_h2;

    const int GEMM_GRID = (NN + 127) / 128;   // 313

    // Edge counts per (dst, relation) — shared by both layers
    cudaMemsetAsync(p_cnt, 0, sizeof(float) * NN * RR, 0);
    count_kernel<<<(EE + 255) / 256, 256>>>(ei, et);
    inv_kernel<<<(NN * RR + 255) / 256, 256>>>();

    // Layer 1
    cudaMemsetAsync(p_sums, 0, sizeof(float) * (size_t)NN * RR * FF, 0);
    scatter_kernel<FF><<<(EE * (FF / 4) + 255) / 256, 256>>>(x, ei, et);
    gemm_kernel<FF><<<GEMM_GRID, 256>>>(x, W1, root1, b1, h1);

    // Layer 2
    cudaMemsetAsync(p_sums, 0, sizeof(float) * (size_t)NN * RR * HH, 0);
    scatter_kernel<HH><<<(EE * (HH / 4) + 255) / 256, 256>>>(h1, ei, et);
    gemm_kernel<HH><<<GEMM_GRID, 256>>>(h1, W2, root2, b2, h2);

    // Global mean pool + FC
    cudaMemsetAsync(p_pool, 0, sizeof(float) * GG * HH, 0);
    cudaMemsetAsync(p_pcnt, 0, sizeof(float) * GG, 0);
    pcnt_kernel<<<(NN + 255) / 256, 256>>>(bat);
    pool_kernel<<<(NN * (HH / 4) + 255) / 256, 256>>>(bat);
    final_kernel<<<GG, CC>>>(fcw, fcb, out);
}

// round 6
// speedup vs baseline: 2.0232x; 1.4331x over previous
#include <cuda_runtime.h>
#include <cuda_bf16.h>
#include <cstdint>

#define NN 40000
#define EE 1280000
#define FF 64
#define HH 128
#define RR 20
#define CC 32
#define GG 256
#define KT_MAX (RR * HH + HH)   // 2688

// ---------------- scratch (static device globals) ----------------
__device__ float g_sums[(size_t)NN * RR * HH];
__device__ float g_cnt[NN * RR];
__device__ float g_inv[NN * RR];
__device__ float g_h1[(size_t)NN * HH];
__device__ float g_h2[(size_t)NN * HH];
__device__ float g_pool[GG * HH];
__device__ float g_pcnt[GG];
__device__ __nv_bfloat16 g_wt_hi[(size_t)HH * KT_MAX];  // [HH, KT] K-major
__device__ __nv_bfloat16 g_wt_lo[(size_t)HH * KT_MAX];

__device__ __forceinline__ uint32_t pack_bf2(float a, float b) {
    __nv_bfloat162 t = __floats2bfloat162_rn(a, b);
    return *reinterpret_cast<uint32_t*>(&t);
}
__device__ __forceinline__ float bf_round(float a) {
    return __bfloat162float(__float2bfloat16_rn(a));
}

// m16n8k16 bf16 MMA, f32 accumulate (baseline PTX ISA — works on sm_100)
__device__ __forceinline__ void mma16816(float* c, uint32_t a0, uint32_t a1,
                                         uint32_t a2, uint32_t a3,
                                         uint32_t b0, uint32_t b1) {
    asm volatile(
        "mma.sync.aligned.m16n8k16.row.col.f32.bf16.bf16.f32 "
        "{%0,%1,%2,%3}, {%4,%5,%6,%7}, {%8,%9}, {%0,%1,%2,%3};"
        : "+f"(c[0]), "+f"(c[1]), "+f"(c[2]), "+f"(c[3])
        : "r"(a0), "r"(a1), "r"(a2), "r"(a3), "r"(b0), "r"(b1));
}

// ---------------- small kernels ----------------
__global__ void count_kernel(const int* __restrict__ ei, const int* __restrict__ et) {
    int e = blockIdx.x * blockDim.x + threadIdx.x;
    if (e >= EE) return;
    atomicAdd(&g_cnt[ei[EE + e] * RR + et[e]], 1.0f);
}

__global__ void inv_kernel() {
    int i = blockIdx.x * blockDim.x + threadIdx.x;
    if (i < NN * RR) g_inv[i] = 1.0f / fmaxf(g_cnt[i], 1.0f);
}

__device__ __forceinline__ void red_add_v4(float* p, float4 v) {
    asm volatile("red.global.add.v4.f32 [%0], {%1, %2, %3, %4};"
                 :: "l"(p), "f"(v.x), "f"(v.y), "f"(v.z), "f"(v.w) : "memory");
}

template <int FIN>
__global__ void scatter_kernel(const float* __restrict__ x,
                               const int* __restrict__ ei,
                               const int* __restrict__ et) {
    constexpr int CPE = FIN / 4;
    long long tid = (long long)blockIdx.x * blockDim.x + threadIdx.x;
    if (tid >= (long long)EE * CPE) return;
    int e = (int)(tid / CPE);
    int c = (int)(tid % CPE);
    int src = ei[e];
    int dst = ei[EE + e];
    int r = et[e];
    float4 v = reinterpret_cast<const float4*>(x + (size_t)src * FIN)[c];
    red_add_v4(&g_sums[(size_t)(dst * RR + r) * FIN + c * 4], v);
}

// Transpose+split weights into bf16 hi/lo, K-major [HH, KT]
__global__ void conv_w_kernel(const float* __restrict__ W,    // [K1, HH]
                              const float* __restrict__ root, // [KT-K1, HH]
                              int K1, int KT) {
    int idx = blockIdx.x * blockDim.x + threadIdx.x;
    if (idx >= HH * KT) return;
    int n = idx / KT;
    int k = idx % KT;
    float v = (k < K1) ? W[(size_t)k * HH + n] : root[(size_t)(k - K1) * HH + n];
    float h = bf_round(v);
    g_wt_hi[(size_t)n * KT + k] = __float2bfloat16_rn(v);
    g_wt_lo[(size_t)n * KT + k] = __float2bfloat16_rn(v - h);
}

// ---------------- mma.sync GEMM ----------------
// out[N,HH] = relu( Ahat[N,K1]@W + xin@root + bias ), fused K = K1 + FIN.
// bf16 hi/lo: D = Ah@Bh + Al@Bh + Ah@Bl.
// Tile: 128x128, BK=32, 8 warps (4m x 2n), warp tile 32x64.
template <int FIN>
__global__ __launch_bounds__(256, 1) void gemm_mma(
    const float* __restrict__ xin, const float* __restrict__ bias,
    float* __restrict__ out) {
    constexpr int K1 = RR * FIN;
    constexpr int KT = K1 + FIN;
    constexpr int BK = 32;
    constexpr int NC = KT / BK;
    constexpr int SHIFT = (FIN == 64) ? 6 : 7;
    constexpr int LDS_K = BK + 8;                 // bf16 units, 80B row stride
    constexpr int MAT = 128 * LDS_K;              // bf16 elems per matrix
    // stage layout (bf16 units): A_hi | A_lo | B_hi | B_lo
    constexpr int STAGE = 4 * MAT;

    extern __shared__ __nv_bfloat16 smem[];

    const int t = threadIdx.x;
    const int wid = t >> 5;
    const int lane = t & 31;
    const int wm = wid & 3;        // warp m index 0..3
    const int wn = wid >> 2;       // warp n index 0..1
    const int m0 = blockIdx.x * 128;

    // per-thread load mapping
    const int lrow = t >> 1;       // 0..127
    const int lhalf = t & 1;       // k half: 0 or 1 (16 k each)
    int rowL = m0 + lrow;
    if (rowL >= NN) rowL = NN - 1;

    float acc[2][8][4];
#pragma unroll
    for (int i = 0; i < 2; i++)
#pragma unroll
        for (int j = 0; j < 8; j++)
#pragma unroll
            for (int q = 0; q < 4; q++) acc[i][j][q] = 0.f;

    float rA[16];
    uint4 rBh[2], rBl[2];

    auto load_chunk = [&](int c) {
        const int k0 = c * BK;
        const float* srcA;
        float s;
        if (k0 < K1) {
            srcA = g_sums + (size_t)rowL * K1 + k0 + lhalf * 16;
            s = g_inv[rowL * RR + (k0 >> SHIFT)];
        } else {
            srcA = xin + (size_t)rowL * FIN + (k0 - K1) + lhalf * 16;
            s = 1.0f;
        }
#pragma unroll
        for (int j = 0; j < 4; j++) {
            float4 v = reinterpret_cast<const float4*>(srcA)[j];
            rA[4 * j + 0] = v.x * s;
            rA[4 * j + 1] = v.y * s;
            rA[4 * j + 2] = v.z * s;
            rA[4 * j + 3] = v.w * s;
        }
        const __nv_bfloat16* sh = g_wt_hi + (size_t)lrow * KT + k0 + lhalf * 16;
        const __nv_bfloat16* sl = g_wt_lo + (size_t)lrow * KT + k0 + lhalf * 16;
        rBh[0] = reinterpret_cast<const uint4*>(sh)[0];
        rBh[1] = reinterpret_cast<const uint4*>(sh)[1];
        rBl[0] = reinterpret_cast<const uint4*>(sl)[0];
        rBl[1] = reinterpret_cast<const uint4*>(sl)[1];
    };

    auto store_chunk = [&](int buf) {
        __nv_bfloat16* base = smem + buf * STAGE;
        uint32_t* aH = reinterpret_cast<uint32_t*>(base + 0 * MAT) +
                       (lrow * LDS_K + lhalf * 16) / 2;
        uint32_t* aL = reinterpret_cast<uint32_t*>(base + 1 * MAT) +
                       (lrow * LDS_K + lhalf * 16) / 2;
#pragma unroll
        for (int j = 0; j < 8; j++) {
            float v0 = rA[2 * j], v1 = rA[2 * j + 1];
            aH[j] = pack_bf2(v0, v1);
            aL[j] = pack_bf2(v0 - bf_round(v0), v1 - bf_round(v1));
        }
        uint4* bH = reinterpret_cast<uint4*>(base + 2 * MAT + lrow * LDS_K + lhalf * 16);
        uint4* bL = reinterpret_cast<uint4*>(base + 3 * MAT + lrow * LDS_K + lhalf * 16);
        bH[0] = rBh[0]; bH[1] = rBh[1];
        bL[0] = rBl[0]; bL[1] = rBl[1];
    };

    auto compute_chunk = [&](int buf) {
        const __nv_bfloat16* base = smem + buf * STAGE;
        const int qrow = lane >> 2;        // 0..7
        const int qk = (lane & 3) * 2;     // 0,2,4,6
#pragma unroll
        for (int ks = 0; ks < 2; ks++) {
            const int kb = ks * 16 + qk;
            uint32_t ah[2][4], al[2][4];
#pragma unroll
            for (int mi = 0; mi < 2; mi++) {
                int r0 = wm * 32 + mi * 16 + qrow;
                const uint32_t* pH = reinterpret_cast<const uint32_t*>(base + 0 * MAT);
                const uint32_t* pL = reinterpret_cast<const uint32_t*>(base + 1 * MAT);
                int i00 = (r0 * LDS_K + kb) / 2;
                int i10 = ((r0 + 8) * LDS_K + kb) / 2;
                ah[mi][0] = pH[i00];     ah[mi][1] = pH[i10];
                ah[mi][2] = pH[i00 + 4]; ah[mi][3] = pH[i10 + 4];
                al[mi][0] = pL[i00];     al[mi][1] = pL[i10];
                al[mi][2] = pL[i00 + 4]; al[mi][3] = pL[i10 + 4];
            }
#pragma unroll
            for (int ni = 0; ni < 8; ni++) {
                int n = wn * 64 + ni * 8 + qrow;
                const uint32_t* pH = reinterpret_cast<const uint32_t*>(base + 2 * MAT);
                const uint32_t* pL = reinterpret_cast<const uint32_t*>(base + 3 * MAT);
                int ib = (n * LDS_K + kb) / 2;
                uint32_t bh0 = pH[ib], bh1 = pH[ib + 4];
                uint32_t bl0 = pL[ib], bl1 = pL[ib + 4];
#pragma unroll
                for (int mi = 0; mi < 2; mi++) {
                    mma16816(acc[mi][ni], ah[mi][0], ah[mi][1], ah[mi][2], ah[mi][3], bh0, bh1);
                    mma16816(acc[mi][ni], al[mi][0], al[mi][1], al[mi][2], al[mi][3], bh0, bh1);
                    mma16816(acc[mi][ni], ah[mi][0], ah[mi][1], ah[mi][2], ah[mi][3], bl0, bl1);
                }
            }
        }
    };

    // prologue
    load_chunk(0);
    store_chunk(0);
    __syncthreads();

    int buf = 0;
    for (int c = 0; c < NC; c++) {
        if (c + 1 < NC) load_chunk(c + 1);
        compute_chunk(buf);
        if (c + 1 < NC) store_chunk(buf ^ 1);
        __syncthreads();
        buf ^= 1;
    }

    // epilogue: bias + relu
    const int qrow = lane >> 2;
    const int qc = (lane & 3) * 2;
#pragma unroll
    for (int mi = 0; mi < 2; mi++) {
#pragma unroll
        for (int ni = 0; ni < 8; ni++) {
            int col = wn * 64 + ni * 8 + qc;
            float b0 = bias[col], b1 = bias[col + 1];
            int r0 = m0 + wm * 32 + mi * 16 + qrow;
            if (r0 < NN) {
                float2 v;
                v.x = fmaxf(acc[mi][ni][0] + b0, 0.f);
                v.y = fmaxf(acc[mi][ni][1] + b1, 0.f);
                *reinterpret_cast<float2*>(&out[(size_t)r0 * HH + col]) = v;
            }
            int r1 = r0 + 8;
            if (r1 < NN) {
                float2 v;
                v.x = fmaxf(acc[mi][ni][2] + b0, 0.f);
                v.y = fmaxf(acc[mi][ni][3] + b1, 0.f);
                *reinterpret_cast<float2*>(&out[(size_t)r1 * HH + col]) = v;
            }
        }
    }
}

// ---------------- pool + fc ----------------
__global__ void pcnt_kernel(const int* __restrict__ batch) {
    int n = blockIdx.x * blockDim.x + threadIdx.x;
    if (n < NN) atomicAdd(&g_pcnt[batch[n]], 1.0f);
}

__global__ void pool_kernel(const int* __restrict__ batch) {
    int tid = blockIdx.x * blockDim.x + threadIdx.x;
    if (tid >= NN * (HH / 4)) return;
    int n = tid / (HH / 4);
    int c = tid % (HH / 4);
    int g = batch[n];
    float4 v = reinterpret_cast<const float4*>(g_h2)[tid];
    red_add_v4(&g_pool[g * HH + c * 4], v);
}

__global__ void final_kernel(const float* __restrict__ fc_w,
                             const float* __restrict__ fc_b,
                             float* __restrict__ out) {
    int g = blockIdx.x;
    int c = threadIdx.x;
    float inv = 1.0f / fmaxf(g_pcnt[g], 1.0f);
    float acc = 0.f;
#pragma unroll 8
    for (int h = 0; h < HH; h++) acc += g_pool[g * HH + h] * fc_w[h * CC + c];
    out[g * CC + c] = acc * inv + fc_b[c];
}

// ---------------- launch ----------------
extern "C" void kernel_launch(void* const* d_in, const int* in_sizes, int n_in,
                              void* d_out, int out_size) {
    const float* x     = (const float*)d_in[0];
    const int* ei      = (const int*)d_in[1];
    const int* et      = (const int*)d_in[2];
    const int* bat     = (const int*)d_in[3];
    const float* W1    = (const float*)d_in[4];
    const float* root1 = (const float*)d_in[5];
    const float* b1    = (const float*)d_in[6];
    const float* W2    = (const float*)d_in[7];
    const float* root2 = (const float*)d_in[8];
    const float* b2    = (const float*)d_in[9];
    const float* fcw   = (const float*)d_in[10];
    const float* fcb   = (const float*)d_in[11];
    float* out         = (float*)d_out;

    void *p_sums, *p_cnt, *p_pool, *p_pcnt, *p_h1, *p_h2;
    cudaGetSymbolAddress(&p_sums, g_sums);
    cudaGetSymbolAddress(&p_cnt, g_cnt);
    cudaGetSymbolAddress(&p_pool, g_pool);
    cudaGetSymbolAddress(&p_pcnt, g_pcnt);
    cudaGetSymbolAddress(&p_h1, g_h1);
    cudaGetSymbolAddress(&p_h2, g_h2);
    float* h1 = (float*)p_h1;
    float* h2 = (float*)p_h2;

    // dynamic smem: 2 stages x 4 matrices x 128 x 40 bf16 = 81920 bytes
    const int DYN = 2 * 4 * 128 * 40 * 2;
    cudaFuncSetAttribute(gemm_mma<FF>, cudaFuncAttributeMaxDynamicSharedMemorySize, DYN);
    cudaFuncSetAttribute(gemm_mma<HH>, cudaFuncAttributeMaxDynamicSharedMemorySize, DYN);

    const int GEMM_GRID = (NN + 127) / 128;   // 313

    // Edge counts per (dst, relation) — shared by both layers
    cudaMemsetAsync(p_cnt, 0, sizeof(float) * NN * RR, 0);
    count_kernel<<<(EE + 255) / 256, 256>>>(ei, et);
    inv_kernel<<<(NN * RR + 255) / 256, 256>>>();

    // Layer 1
    cudaMemsetAsync(p_sums, 0, sizeof(float) * (size_t)NN * RR * FF, 0);
    conv_w_kernel<<<(HH * (RR * FF + FF) + 255) / 256, 256>>>(W1, root1, RR * FF, RR * FF + FF);
    scatter_kernel<FF><<<(EE * (FF / 4) + 255) / 256, 256>>>(x, ei, et);
    gemm_mma<FF><<<GEMM_GRID, 256, DYN>>>(x, b1, h1);

    // Layer 2
    cudaMemsetAsync(p_sums, 0, sizeof(float) * (size_t)NN * RR * HH, 0);
    conv_w_kernel<<<(HH * (RR * HH + HH) + 255) / 256, 256>>>(W2, root2, RR * HH, RR * HH + HH);
    scatter_kernel<HH><<<(EE * (HH / 4) + 255) / 256, 256>>>(h1, ei, et);
    gemm_mma<HH><<<GEMM_GRID, 256, DYN>>>(h1, b2, h2);

    // Global mean pool + FC
    cudaMemsetAsync(p_pool, 0, sizeof(float) * GG * HH, 0);
    cudaMemsetAsync(p_pcnt, 0, sizeof(float) * GG, 0);
    pcnt_kernel<<<(NN + 255) / 256, 256>>>(bat);
    pool_kernel<<<(NN * (HH / 4) + 255) / 256, 256>>>(bat);
    final_kernel<<<GG, CC>>>(fcw, fcb, out);
}

// round 9
// speedup vs baseline: 2.3336x; 1.1534x over previous
#include <cuda_runtime.h>
#include <cuda_bf16.h>
#include <cstdint>

#define NN 40000
#define EE 1280000
#define FF 64
#define HH 128
#define RR 20
#define CC 32
#define GG 256
#define KT_MAX (RR * HH + HH)   // 2688

// ---------------- scratch (static device globals) ----------------
__device__ float g_sums[(size_t)NN * RR * HH];
__device__ float g_cnt[NN * RR];
__device__ float g_inv[NN * RR];
__device__ float g_h1[(size_t)NN * HH];
__device__ float g_h2[(size_t)NN * HH];
__device__ float g_pool[GG * HH];
__device__ float g_pcnt[GG];
__device__ __nv_bfloat16 g_wt_hi[(size_t)HH * KT_MAX];  // [HH, KT] K-major
__device__ __nv_bfloat16 g_wt_lo[(size_t)HH * KT_MAX];

__device__ __forceinline__ uint32_t pack_bf2(float a, float b) {
    __nv_bfloat162 t = __floats2bfloat162_rn(a, b);
    return *reinterpret_cast<uint32_t*>(&t);
}
__device__ __forceinline__ float bf_round(float a) {
    return __bfloat162float(__float2bfloat16_rn(a));
}

__device__ __forceinline__ void mma16816(float* c, uint32_t a0, uint32_t a1,
                                         uint32_t a2, uint32_t a3,
                                         uint32_t b0, uint32_t b1) {
    asm volatile(
        "mma.sync.aligned.m16n8k16.row.col.f32.bf16.bf16.f32 "
        "{%0,%1,%2,%3}, {%4,%5,%6,%7}, {%8,%9}, {%0,%1,%2,%3};"
        : "+f"(c[0]), "+f"(c[1]), "+f"(c[2]), "+f"(c[3])
        : "r"(a0), "r"(a1), "r"(a2), "r"(a3), "r"(b0), "r"(b1));
}
__device__ __forceinline__ void ldm_x4(uint32_t& r0, uint32_t& r1,
                                       uint32_t& r2, uint32_t& r3, uint32_t sa) {
    asm volatile("ldmatrix.sync.aligned.m8n8.x4.shared.b16 {%0,%1,%2,%3}, [%4];"
                 : "=r"(r0), "=r"(r1), "=r"(r2), "=r"(r3) : "r"(sa));
}
__device__ __forceinline__ void cp_async16(uint32_t sa, const void* g) {
    asm volatile("cp.async.cg.shared.global [%0], [%1], 16;" :: "r"(sa), "l"(g));
}
__device__ __forceinline__ void cp_commit() {
    asm volatile("cp.async.commit_group;" ::: "memory");
}
__device__ __forceinline__ void cp_wait0() {
    asm volatile("cp.async.wait_group 0;" ::: "memory");
}

// ---------------- small kernels ----------------
__global__ void count_kernel(const int* __restrict__ ei, const int* __restrict__ et) {
    int e = blockIdx.x * blockDim.x + threadIdx.x;
    if (e >= EE) return;
    atomicAdd(&g_cnt[ei[EE + e] * RR + et[e]], 1.0f);
}

__global__ void inv_kernel() {
    int i = blockIdx.x * blockDim.x + threadIdx.x;
    if (i < NN * RR) g_inv[i] = 1.0f / fmaxf(g_cnt[i], 1.0f);
}

__device__ __forceinline__ void red_add_v4(float* p, float4 v) {
    asm volatile("red.global.add.v4.f32 [%0], {%1, %2, %3, %4};"
                 :: "l"(p), "f"(v.x), "f"(v.y), "f"(v.z), "f"(v.w) : "memory");
}

template <int FIN>
__global__ void scatter_kernel(const float* __restrict__ x,
                               const int* __restrict__ ei,
                               const int* __restrict__ et) {
    constexpr int CPE = FIN / 4;
    long long tid = (long long)blockIdx.x * blockDim.x + threadIdx.x;
    if (tid >= (long long)EE * CPE) return;
    int e = (int)(tid / CPE);
    int c = (int)(tid % CPE);
    int src = ei[e];
    int dst = ei[EE + e];
    int r = et[e];
    float4 v = reinterpret_cast<const float4*>(x + (size_t)src * FIN)[c];
    red_add_v4(&g_sums[(size_t)(dst * RR + r) * FIN + c * 4], v);
}

// Tiled transpose+split: W[k][n] (+root tail) -> g_wt_{hi,lo}[n][k], coalesced.
__global__ void conv_w_kernel(const float* __restrict__ W,
                              const float* __restrict__ root,
                              int K1, int KT) {
    __shared__ float tile[32][33];
    int kb = blockIdx.x * 32, nb = blockIdx.y * 32;
    int tx = threadIdx.x, ty = threadIdx.y;
#pragma unroll
    for (int i = 0; i < 4; i++) {
        int k = kb + ty + i * 8;
        float v = (k < K1) ? W[(size_t)k * HH + nb + tx]
                           : root[(size_t)(k - K1) * HH + nb + tx];
        tile[ty + i * 8][tx] = v;
    }
    __syncthreads();
#pragma unroll
    for (int i = 0; i < 4; i++) {
        int n = nb + ty + i * 8;
        int k = kb + tx;
        float v = tile[tx][ty + i * 8];
        float h = bf_round(v);
        g_wt_hi[(size_t)n * KT + k] = __float2bfloat16_rn(v);
        g_wt_lo[(size_t)n * KT + k] = __float2bfloat16_rn(v - h);
    }
}

// ---------------- mma.sync GEMM (ldmatrix + cp.async, occ 2) ----------------
// out[N,HH] = relu( Ahat[N,K1]@W + xin@root + bias ), fused K = K1 + FIN.
// bf16 hi/lo: D = Ah@Bh + Al@Bh + Ah@Bl.  Tile 128x128, BK=32, 8 warps (4m x 2n).
template <int FIN>
__global__ __launch_bounds__(256, 2) void gemm_mma(
    const float* __restrict__ xin, const float* __restrict__ bias,
    float* __restrict__ out) {
    constexpr int K1 = RR * FIN;
    constexpr int KT = K1 + FIN;
    constexpr int BK = 32;
    constexpr int NC = KT / BK;
    constexpr int SHIFT = (FIN == 64) ? 6 : 7;
    constexpr int LDS_K = BK + 8;               // bf16 units (80B row)
    constexpr int MAT = 128 * LDS_K;            // elems per matrix
    constexpr int STAGE_E = 4 * MAT;            // elems per stage (AH|AL|BH|BL)
    constexpr uint32_t STAGE_B = STAGE_E * 2;   // bytes

    extern __shared__ __align__(16) __nv_bfloat16 smem[];

    const int t = threadIdx.x;
    const int wid = t >> 5;
    const int lane = t & 31;
    const int wm = wid & 3;
    const int wn = wid >> 2;
    const int m0 = blockIdx.x * 128;

    const int lrow = t >> 1;
    const int lhalf = t & 1;
    int rowL = m0 + lrow;
    if (rowL >= NN) rowL = NN - 1;

    const uint32_t sbase = (uint32_t)__cvta_generic_to_shared(smem);

    float acc[2][8][4];
#pragma unroll
    for (int i = 0; i < 2; i++)
#pragma unroll
        for (int j = 0; j < 8; j++)
#pragma unroll
            for (int q = 0; q < 4; q++) acc[i][j][q] = 0.f;

    float rA[16];

    auto issue_B = [&](int c, int buf) {
        const int k0 = c * BK;
        const int row = t >> 1;
        const int seg = (t & 1) * 2;             // 2 of 4 16B segs per row
        const __nv_bfloat16* gh = g_wt_hi + (size_t)row * KT + k0 + seg * 8;
        const __nv_bfloat16* gl = g_wt_lo + (size_t)row * KT + k0 + seg * 8;
        uint32_t sh = sbase + buf * STAGE_B + (uint32_t)(2 * MAT + row * LDS_K + seg * 8) * 2;
        uint32_t sl = sbase + buf * STAGE_B + (uint32_t)(3 * MAT + row * LDS_K + seg * 8) * 2;
        cp_async16(sh, gh);       cp_async16(sh + 16, gh + 8);
        cp_async16(sl, gl);       cp_async16(sl + 16, gl + 8);
    };

    auto ldg_A = [&](int c) {
        const int k0 = c * BK;
        const float* src;
        float s;
        if (k0 < K1) {
            src = g_sums + (size_t)rowL * K1 + k0 + lhalf * 16;
            s = g_inv[rowL * RR + (k0 >> SHIFT)];
        } else {
            src = xin + (size_t)rowL * FIN + (k0 - K1) + lhalf * 16;
            s = 1.0f;
        }
#pragma unroll
        for (int j = 0; j < 4; j++) {
            float4 v = reinterpret_cast<const float4*>(src)[j];
            rA[4 * j + 0] = v.x * s;
            rA[4 * j + 1] = v.y * s;
            rA[4 * j + 2] = v.z * s;
            rA[4 * j + 3] = v.w * s;
        }
    };

    auto sts_A = [&](int buf) {
        uint32_t h[8], l[8];
#pragma unroll
        for (int j = 0; j < 8; j++) {
            float v0 = rA[2 * j], v1 = rA[2 * j + 1];
            h[j] = pack_bf2(v0, v1);
            l[j] = pack_bf2(v0 - bf_round(v0), v1 - bf_round(v1));
        }
        __nv_bfloat16* base = smem + buf * STAGE_E + lrow * LDS_K + lhalf * 16;
        reinterpret_cast<uint4*>(base)[0] = make_uint4(h[0], h[1], h[2], h[3]);
        reinterpret_cast<uint4*>(base)[1] = make_uint4(h[4], h[5], h[6], h[7]);
        reinterpret_cast<uint4*>(base + MAT)[0] = make_uint4(l[0], l[1], l[2], l[3]);
        reinterpret_cast<uint4*>(base + MAT)[1] = make_uint4(l[4], l[5], l[6], l[7]);
    };

    const int lmat = lane >> 3;   // which 8x8 within ldmatrix.x4
    const int lr = lane & 7;

    auto compute = [&](int buf) {
        const uint32_t s = sbase + buf * STAGE_B;
#pragma unroll
        for (int ks = 0; ks < 2; ks++) {
            const int kb = ks * 16;
            uint32_t ah[2][4], al[2][4];
#pragma unroll
            for (int mi = 0; mi < 2; mi++) {
                int arow = wm * 32 + mi * 16 + (lmat & 1) * 8 + lr;
                int ak = kb + (lmat >> 1) * 8;
                uint32_t aH = s + (uint32_t)(arow * LDS_K + ak) * 2;
                ldm_x4(ah[mi][0], ah[mi][1], ah[mi][2], ah[mi][3], aH);
                ldm_x4(al[mi][0], al[mi][1], al[mi][2], al[mi][3], aH + MAT * 2);
            }
#pragma unroll
            for (int g = 0; g < 4; g++) {
                int brow = wn * 64 + (2 * g + (lmat >> 1)) * 8 + lr;
                int bk = kb + (lmat & 1) * 8;
                uint32_t bB = s + (uint32_t)(2 * MAT + brow * LDS_K + bk) * 2;
                uint32_t bh[4], bl[4];
                ldm_x4(bh[0], bh[1], bh[2], bh[3], bB);
                ldm_x4(bl[0], bl[1], bl[2], bl[3], bB + MAT * 2);
#pragma unroll
                for (int sub = 0; sub < 2; sub++) {
                    int ni = 2 * g + sub;
                    uint32_t b0h = bh[2 * sub], b1h = bh[2 * sub + 1];
                    uint32_t b0l = bl[2 * sub], b1l = bl[2 * sub + 1];
#pragma unroll
                    for (int mi = 0; mi < 2; mi++) {
                        mma16816(acc[mi][ni], ah[mi][0], ah[mi][1], ah[mi][2], ah[mi][3], b0h, b1h);
                        mma16816(acc[mi][ni], al[mi][0], al[mi][1], al[mi][2], al[mi][3], b0h, b1h);
                        mma16816(acc[mi][ni], ah[mi][0], ah[mi][1], ah[mi][2], ah[mi][3], b0l, b1l);
                    }
                }
            }
        }
    };

    // prologue
    issue_B(0, 0);
    cp_commit();
    ldg_A(0);
    sts_A(0);
    cp_wait0();
    __syncthreads();

    int buf = 0;
    for (int c = 0; c < NC; c++) {
        if (c + 1 < NC) {
            issue_B(c + 1, buf ^ 1);
            cp_commit();
            ldg_A(c + 1);
        }
        compute(buf);
        if (c + 1 < NC) {
            sts_A(buf ^ 1);
            cp_wait0();
        }
        __syncthreads();
        buf ^= 1;
    }

    // epilogue: bias + relu
    const int qrow = lane >> 2;
    const int qc = (lane & 3) * 2;
#pragma unroll
    for (int mi = 0; mi < 2; mi++) {
#pragma unroll
        for (int ni = 0; ni < 8; ni++) {
            int col = wn * 64 + ni * 8 + qc;
            float b0 = bias[col], b1 = bias[col + 1];
            int r0 = m0 + wm * 32 + mi * 16 + qrow;
            if (r0 < NN) {
                float2 v;
                v.x = fmaxf(acc[mi][ni][0] + b0, 0.f);
                v.y = fmaxf(acc[mi][ni][1] + b1, 0.f);
                *reinterpret_cast<float2*>(&out[(size_t)r0 * HH + col]) = v;
            }
            int r1 = r0 + 8;
            if (r1 < NN) {
                float2 v;
                v.x = fmaxf(acc[mi][ni][2] + b0, 0.f);
                v.y = fmaxf(acc[mi][ni][3] + b1, 0.f);
                *reinterpret_cast<float2*>(&out[(size_t)r1 * HH + col]) = v;
            }
        }
    }
}

// ---------------- pool + fc ----------------
__global__ void pcnt_kernel(const int* __restrict__ batch) {
    int n = blockIdx.x * blockDim.x + threadIdx.x;
    if (n < NN) atomicAdd(&g_pcnt[batch[n]], 1.0f);
}

__global__ void pool_kernel(const int* __restrict__ batch) {
    int tid = blockIdx.x * blockDim.x + threadIdx.x;
    if (tid >= NN * (HH / 4)) return;
    int n = tid / (HH / 4);
    int c = tid % (HH / 4);
    int g = batch[n];
    float4 v = reinterpret_cast<const float4*>(g_h2)[tid];
    red_add_v4(&g_pool[g * HH + c * 4], v);
}

__global__ void final_kernel(const float* __restrict__ fc_w,
                             const float* __restrict__ fc_b,
                             float* __restrict__ out) {
    int g = blockIdx.x;
    int c = threadIdx.x;
    float inv = 1.0f / fmaxf(g_pcnt[g], 1.0f);
    float acc = 0.f;
#pragma unroll 8
    for (int h = 0; h < HH; h++) acc += g_pool[g * HH + h] * fc_w[h * CC + c];
    out[g * CC + c] = acc * inv + fc_b[c];
}

// ---------------- launch ----------------
extern "C" void kernel_launch(void* const* d_in, const int* in_sizes, int n_in,
                              void* d_out, int out_size) {
    const float* x     = (const float*)d_in[0];
    const int* ei      = (const int*)d_in[1];
    const int* et      = (const int*)d_in[2];
    const int* bat     = (const int*)d_in[3];
    const float* W1    = (const float*)d_in[4];
    const float* root1 = (const float*)d_in[5];
    const float* b1    = (const float*)d_in[6];
    const float* W2    = (const float*)d_in[7];
    const float* root2 = (const float*)d_in[8];
    const float* b2    = (const float*)d_in[9];
    const float* fcw   = (const float*)d_in[10];
    const float* fcb   = (const float*)d_in[11];
    float* out         = (float*)d_out;

    void *p_sums, *p_cnt, *p_pool, *p_pcnt, *p_h1, *p_h2;
    cudaGetSymbolAddress(&p_sums, g_sums);
    cudaGetSymbolAddress(&p_cnt, g_cnt);
    cudaGetSymbolAddress(&p_pool, g_pool);
    cudaGetSymbolAddress(&p_pcnt, g_pcnt);
    cudaGetSymbolAddress(&p_h1, g_h1);
    cudaGetSymbolAddress(&p_h2, g_h2);
    float* h1 = (float*)p_h1;
    float* h2 = (float*)p_h2;

    // dyn smem: 2 stages x 4 mats x 128 x 40 bf16 = 81920 B  (2 CTAs/SM)
    const int DYN = 2 * 4 * 128 * 40 * 2;
    cudaFuncSetAttribute(gemm_mma<FF>, cudaFuncAttributeMaxDynamicSharedMemorySize, DYN);
    cudaFuncSetAttribute(gemm_mma<HH>, cudaFuncAttributeMaxDynamicSharedMemorySize, DYN);

    const int GEMM_GRID = (NN + 127) / 128;   // 313

    cudaMemsetAsync(p_cnt, 0, sizeof(float) * NN * RR, 0);
    count_kernel<<<(EE + 255) / 256, 256>>>(ei, et);
    inv_kernel<<<(NN * RR + 255) / 256, 256>>>();

    // Layer 1
    cudaMemsetAsync(p_sums, 0, sizeof(float) * (size_t)NN * RR * FF, 0);
    {
        dim3 grid((RR * FF + FF) / 32, HH / 32), blk(32, 8);
        conv_w_kernel<<<grid, blk>>>(W1, root1, RR * FF, RR * FF + FF);
    }
    scatter_kernel<FF><<<(EE * (FF / 4) + 255) / 256, 256>>>(x, ei, et);
    gemm_mma<FF><<<GEMM_GRID, 256, DYN>>>(x, b1, h1);

    // Layer 2
    cudaMemsetAsync(p_sums, 0, sizeof(float) * (size_t)NN * RR * HH, 0);
    {
        dim3 grid((RR * HH + HH) / 32, HH / 32), blk(32, 8);
        conv_w_kernel<<<grid, blk>>>(W2, root2, RR * HH, RR * HH + HH);
    }
    scatter_kernel<HH><<<(EE * (HH / 4) + 255) / 256, 256>>>(h1, ei, et);
    gemm_mma<HH><<<GEMM_GRID, 256, DYN>>>(h1, b2, h2);

    // Global mean pool + FC
    cudaMemsetAsync(p_pool, 0, sizeof(float) * GG * HH, 0);
    cudaMemsetAsync(p_pcnt, 0, sizeof(float) * GG, 0);
    pcnt_kernel<<<(NN + 255) / 256, 256>>>(bat);
    pool_kernel<<<(NN * (HH / 4) + 255) / 256, 256>>>(bat);
    final_kernel<<<GG, CC>>>(fcw, fcb, out);
}